// round 9
// baseline (speedup 1.0000x reference)
#include <cuda_runtime.h>

// N = 2^26 FFT of REAL fp32 input via half-length complex FFT (M = 2^25):
//   z[n] = x[2n] + i x[2n+1]  (free reinterpret), Z = FFT_M(z), Hermitian unpack.
//   P1:  radix-256, s=1      z -> D   (d_out as complex scratch)   [verified]
//   P2:  radix-256, s=256    D -> B   (g_buf)                      [verified]
//   P3U: radix-512 final (s=2^16) fused with unpack: B -> planar out.
//        512 threads, 8 A-groups + 8 mirror B-groups, 65.7KB smem,
//        2 blocks/SM (fixes round-8's 1-block/SM serialization).

#define NFFT  (1u << 26)
#define MFFT  (1u << 25)
#define M256  (1u << 17)   // MFFT / 256
#define S512  (1u << 16)   // MFFT / 512
#define TWO_PI 6.28318530717958647692f
#define INVM  (1.0f / 33554432.0f)
#define INVN  (1.0f / 67108864.0f)

static __device__ float2 g_buf[MFFT];  // 256 MB scratch (sanctioned)

// exp(-2*pi*i*j/256), j = 0..15
__constant__ float2 c_w256[16] = {
    { 1.00000000000000000f, -0.00000000000000000f},
    { 0.99969881869620422f, -0.02454122852291229f},
    { 0.99879545620517241f, -0.04906767432741801f},
    { 0.99729045667869021f, -0.07356456359966743f},
    { 0.99518472667219693f, -0.09801714032956060f},
    { 0.99247953459870997f, -0.12241067519921620f},
    { 0.98917650996478101f, -0.14673047445536175f},
    { 0.98527764238894122f, -0.17096188876030122f},
    { 0.98078528040323044f, -0.19509032201612825f},
    { 0.97570213003852857f, -0.21910124015686980f},
    { 0.97003125319454397f, -0.24298017990326390f},
    { 0.96377606579543984f, -0.26671275747489837f},
    { 0.95694033573220882f, -0.29028467725446233f},
    { 0.94952818059303667f, -0.31368174039889152f},
    { 0.94154406518302081f, -0.33688985339222005f},
    { 0.93299279883473896f, -0.35989503653498817f}
};
// exp(-2*pi*i*k/32), k = 0..15
__constant__ float2 c_w32[16] = {
    { 1.00000000000000000f, -0.00000000000000000f},
    { 0.98078528040323045f, -0.19509032201612827f},
    { 0.92387953251128676f, -0.38268343236508977f},
    { 0.83146961230254524f, -0.55557023301960222f},
    { 0.70710678118654752f, -0.70710678118654752f},
    { 0.55557023301960222f, -0.83146961230254524f},
    { 0.38268343236508977f, -0.92387953251128676f},
    { 0.19509032201612827f, -0.98078528040323045f},
    { 0.00000000000000000f, -1.00000000000000000f},
    {-0.19509032201612827f, -0.98078528040323045f},
    {-0.38268343236508977f, -0.92387953251128676f},
    {-0.55557023301960222f, -0.83146961230254524f},
    {-0.70710678118654752f, -0.70710678118654752f},
    {-0.83146961230254524f, -0.55557023301960222f},
    {-0.92387953251128676f, -0.38268343236508977f},
    {-0.98078528040323045f, -0.19509032201612827f}
};

__device__ __forceinline__ float2 cmul(float2 a, float2 b) {
    return make_float2(a.x * b.x - a.y * b.y, a.x * b.y + a.y * b.x);
}
__device__ __forceinline__ float2 cadd(float2 a, float2 b) {
    return make_float2(a.x + b.x, a.y + b.y);
}
__device__ __forceinline__ float2 csub(float2 a, float2 b) {
    return make_float2(a.x - b.x, a.y - b.y);
}
__device__ __forceinline__ float2 cmul_negi(float2 a) { return make_float2(a.y, -a.x); }
__device__ __forceinline__ float2 cmul_posi(float2 a) { return make_float2(-a.y, a.x); }

// In-place forward DFT-16, natural order in/out (verified rounds 2-8).
__device__ __forceinline__ void dft16(float2 a[16]) {
    const float C1 = 0.92387953251128675613f;
    const float S1 = 0.38268343236508977173f;
    const float H  = 0.70710678118654752440f;
    const float2 W1 = make_float2( C1, -S1);
    const float2 W2 = make_float2(  H,  -H);
    const float2 W3 = make_float2( S1, -C1);
    const float2 W4 = make_float2(0.f, -1.f);
    const float2 W6 = make_float2( -H,  -H);
    const float2 W9 = make_float2(-C1,  S1);
    float2 b[16];
#pragma unroll
    for (int r1 = 0; r1 < 4; ++r1) {
        float2 x0 = a[r1], x1 = a[r1 + 4], x2 = a[r1 + 8], x3 = a[r1 + 12];
        float2 e = cadd(x0, x2), f = csub(x0, x2);
        float2 g = cadd(x1, x3), h = csub(x1, x3);
        b[r1 * 4 + 0] = cadd(e, g);
        b[r1 * 4 + 1] = cadd(f, cmul_negi(h));
        b[r1 * 4 + 2] = csub(e, g);
        b[r1 * 4 + 3] = cadd(f, cmul_posi(h));
    }
    b[5]  = cmul(b[5],  W1);
    b[6]  = cmul(b[6],  W2);
    b[7]  = cmul(b[7],  W3);
    b[9]  = cmul(b[9],  W2);
    b[10] = cmul(b[10], W4);
    b[11] = cmul(b[11], W6);
    b[13] = cmul(b[13], W3);
    b[14] = cmul(b[14], W6);
    b[15] = cmul(b[15], W9);
#pragma unroll
    for (int k1 = 0; k1 < 4; ++k1) {
        float2 x0 = b[k1], x1 = b[4 + k1], x2 = b[8 + k1], x3 = b[12 + k1];
        float2 e = cadd(x0, x2), f = csub(x0, x2);
        float2 g = cadd(x1, x3), h = csub(x1, x3);
        a[k1 + 0]  = cadd(e, g);
        a[k1 + 4]  = cadd(f, cmul_negi(h));
        a[k1 + 8]  = csub(e, g);
        a[k1 + 12] = cadd(f, cmul_posi(h));
    }
}

__device__ __forceinline__ unsigned swz(unsigned l) { return l + (l >> 8); }

// ---------------------------------------------------------------------------
// P1: radix-256, s=1, complex input (verified rounds 7-8).
// ---------------------------------------------------------------------------
__global__ void __launch_bounds__(256) fft256_first(const float2* __restrict__ x,
                                                    float2* __restrict__ y) {
    __shared__ float2 sm[4112];
    unsigned tid = threadIdx.x;
    unsigned g = tid & 15u, j2 = tid >> 4;
    unsigned t = blockIdx.x * 16u + g;

    float2 a[16];
#pragma unroll
    for (int i = 0; i < 16; ++i) a[i] = x[t + (16u * (unsigned)i + j2) * M256];
    dft16(a);

    float sn, cs;
    __sincosf(-TWO_PI * (float)t * INVM, &sn, &cs);
    float2 wg = make_float2(cs, sn);
    float2 w1 = cmul(c_w256[j2], wg);
    float2 w = make_float2(1.f, 0.f);
#pragma unroll
    for (int k1 = 0; k1 < 16; ++k1) {
        sm[swz(tid + 256u * (unsigned)k1)] = cmul(a[k1], w);
        w = cmul(w, w1);
    }
    __syncthreads();

    unsigned k1p = tid >> 4;
#pragma unroll
    for (int j = 0; j < 16; ++j)
        a[j] = sm[swz(256u * k1p + 16u * (unsigned)j + g)];
    dft16(a);

    float2 w2 = cmul(wg, wg);
    w2 = cmul(w2, w2); w2 = cmul(w2, w2); w2 = cmul(w2, w2);  // wg^16
    float2 r[16];
    w = make_float2(1.f, 0.f);
#pragma unroll
    for (int k2 = 0; k2 < 16; ++k2) { r[k2] = cmul(a[k2], w); w = cmul(w, w2); }

    __syncthreads();
#pragma unroll
    for (int k2 = 0; k2 < 16; ++k2)
        sm[swz(256u * g + k1p + 16u * (unsigned)k2)] = r[k2];
    __syncthreads();

    unsigned base = blockIdx.x * 4096u;
#pragma unroll
    for (int i = 0; i < 16; ++i) {
        unsigned m = tid + 256u * (unsigned)i;
        y[base + m] = sm[swz(m)];
    }
}

// ---------------------------------------------------------------------------
// P2: radix-256 mid stage, log2s = 8 (verified rounds 7-8).
// ---------------------------------------------------------------------------
__global__ void __launch_bounds__(256) fft256_mid(const float2* __restrict__ x,
                                                  float2* __restrict__ y,
                                                  int log2s) {
    __shared__ float2 sm[4112];
    unsigned tid = threadIdx.x;
    unsigned g = tid & 15u, j2 = tid >> 4;
    unsigned t = blockIdx.x * 16u + g;
    unsigned s = 1u << log2s;
    unsigned q = t & (s - 1u);
    unsigned ps = t - q;

    float2 a[16];
#pragma unroll
    for (int i = 0; i < 16; ++i) a[i] = x[t + (16u * (unsigned)i + j2) * M256];
    dft16(a);

    float sn, cs;
    __sincosf(-TWO_PI * (float)ps * INVM, &sn, &cs);
    float2 wg = make_float2(cs, sn);
    float2 w1 = cmul(c_w256[j2], wg);
    float2 w = make_float2(1.f, 0.f);
#pragma unroll
    for (int k1 = 0; k1 < 16; ++k1) {
        sm[swz(tid + 256u * (unsigned)k1)] = cmul(a[k1], w);
        w = cmul(w, w1);
    }
    __syncthreads();

    unsigned k1p = tid >> 4;
#pragma unroll
    for (int j = 0; j < 16; ++j)
        a[j] = sm[swz(256u * k1p + 16u * (unsigned)j + g)];
    dft16(a);

    float2 w2 = cmul(wg, wg);
    w2 = cmul(w2, w2); w2 = cmul(w2, w2); w2 = cmul(w2, w2);
    unsigned base = q + (ps << 8) + (k1p << log2s);
    w = make_float2(1.f, 0.f);
#pragma unroll
    for (int k2 = 0; k2 < 16; ++k2) {
        y[base + ((unsigned)k2 << (log2s + 4))] = cmul(a[k2], w);
        w = cmul(w, w2);
    }
}

// ---------------------------------------------------------------------------
// P3U: radix-512 final stage (s=2^16, twiddle-free) fused with Hermitian
// unpack. Block = 512 threads = 16 groups (8 A-chunk + 8 mirror B-chunk),
// each group a full 512-point FFT held in smem. Then per m = t + k*S512
// (t in A): A=(Z[m]+conj Z[M-m])/2, B=-i(Z[m]-conj Z[M-m])/2, W=e^{-2pi i m/N},
// P=A+WB -> X[m], conj P -> X[N-m], Q=A-WB -> X[M+m], conj Q -> X[M-m].
// Grid 4097: blocks 0..4095 cover t in [0,32768); block 4096 covers the
// self-mirror chunk (duplicate writes are mathematically identical, benign).
// ---------------------------------------------------------------------------
#define GSK 513u
__global__ void __launch_bounds__(512, 2) fft512_unpack(const float2* __restrict__ x,
                                                        float* __restrict__ out) {
    extern __shared__ float2 sm[];
    const unsigned tid = threadIdx.x;
    const unsigned bb = blockIdx.x;

    // ======================= FFT phase (16 groups) =======================
    {
        const unsigned gg = tid & 7u;
        const unsigned u = (tid >> 3) & 31u;
        const unsigned half = tid >> 8;
        const unsigned tA = 8u * bb + gg;
        const unsigned tB = (S512 - 8u * bb - 7u + gg) & (S512 - 1u);
        const unsigned t = half ? tB : tA;
        const unsigned gb = (half * 8u + gg) * GSK;

        float2 a[16];
#pragma unroll
        for (int j = 0; j < 16; ++j) a[j] = x[t + (u + 32u * (unsigned)j) * S512];

        // SA: radix-16, s=1
        dft16(a);
        {
            float sn, cs;
            __sincosf(-TWO_PI * (float)u * (1.0f / 512.0f), &sn, &cs);
            float2 wa = make_float2(cs, sn), w = make_float2(1.f, 0.f);
#pragma unroll
            for (int k = 0; k < 16; ++k) {
                sm[gb + 16u * u + (unsigned)k] = cmul(a[k], w);
                w = cmul(w, wa);
            }
        }
        __syncthreads();

        // SB: radix-16, s=16
#pragma unroll
        for (int j = 0; j < 16; ++j) a[j] = sm[gb + u + 32u * (unsigned)j];
        dft16(a);
        __syncthreads();
        {
            unsigned q15 = u & 15u, p = u >> 4;
#pragma unroll
            for (int k = 0; k < 16; ++k) {
                float2 v = (p == 0u) ? a[k] : cmul(a[k], c_w32[k]);
                sm[gb + q15 + 256u * p + 16u * (unsigned)k] = v;
            }
        }
        __syncthreads();

        // SC: radix-2, s=256, in-place (same-thread read+write)
#pragma unroll
        for (int i = 0; i < 8; ++i) {
            unsigned t2 = u + 32u * (unsigned)i;
            float2 b0 = sm[gb + t2];
            float2 b1 = sm[gb + t2 + 256u];
            sm[gb + t2]        = cadd(b0, b1);
            sm[gb + t2 + 256u] = csub(b0, b1);
        }
    }
    __syncthreads();

    // ======================= unpack phase =======================
    {
        const unsigned gA = tid & 7u;
        const unsigned uu = tid >> 3;          // [0, 64)
        const unsigned t = 8u * bb + gA;       // A-group t (< S512)
        const unsigned gbA = gA * GSK;
        const unsigned gbB = (15u - gA) * GSK; // mirror group (B half)
        const bool tzero = (t == 0u);

        float m0f = (float)(t + uu * S512);
        float sn, cs;
        __sincosf(-TWO_PI * m0f * INVN, &sn, &cs);
        float2 W = make_float2(cs, sn);
        const float2 Winc = c_w32[2];          // e^{-2pi i/16}: k += 64 step

#pragma unroll
        for (int j = 0; j < 8; ++j) {
            unsigned k = uu + 64u * (unsigned)j;
            float2 Zk = sm[gbA + k];
            unsigned kp = tzero ? ((512u - k) & 511u) : (511u - k);
            float2 Zm = sm[gbB + kp];

            float2 A = make_float2(0.5f * (Zk.x + Zm.x), 0.5f * (Zk.y - Zm.y));
            float2 C = make_float2(0.5f * (Zk.x - Zm.x), 0.5f * (Zk.y + Zm.y));
            float2 B = make_float2(C.y, -C.x);
            float2 WB = cmul(W, B);
            float2 P = cadd(A, WB);
            float2 Q = csub(A, WB);

            unsigned m = t + k * S512;               // [0, M)
            unsigned i3 = (NFFT - m) & (NFFT - 1u);  // N - m (mod N)
            unsigned i2 = MFFT - m;
            unsigned i4 = MFFT + m;

            out[m]  = P.x;   out[NFFT + m]  = P.y;
            out[i3] = P.x;   out[NFFT + i3] = -P.y;
            out[i2] = Q.x;   out[NFFT + i2] = -Q.y;
            out[i4] = Q.x;   out[NFFT + i4] = Q.y;

            W = cmul(W, Winc);
        }
    }
}

// ---------------------------------------------------------------------------
// Schedule: P1: z -> D (d_out scratch); P2: D -> B (g_buf); P3U: B -> out.
// P3U reads only g_buf, writes only d_out: no aliasing hazard.
// ---------------------------------------------------------------------------
extern "C" void kernel_launch(void* const* d_in, const int* in_sizes, int n_in,
                              void* d_out, int out_size) {
    const float2* z = (const float2*)d_in[0];   // N reals = M complex (free pack)
    float* out = (float*)d_out;
    float2* D = (float2*)d_out;                 // M float2 scratch fits in out
    float2* B = nullptr;
    cudaGetSymbolAddress((void**)&B, g_buf);

    const size_t smem3 = (size_t)(16u * GSK) * sizeof(float2);  // 65,664 B
    cudaFuncSetAttribute(fft512_unpack,
                         cudaFuncAttributeMaxDynamicSharedMemorySize, (int)smem3);

    fft256_first <<<M256 / 16u, 256>>>(z, D);                 // 8192 blocks
    fft256_mid   <<<M256 / 16u, 256>>>(D, B, 8);              // 8192 blocks
    fft512_unpack<<<S512 / 8u / 2u + 1u, 512, smem3>>>(B, out);  // 4097 blocks
}

// round 10
// speedup vs baseline: 1.0674x; 1.0674x over previous
#include <cuda_runtime.h>

// N = 2^26 FFT of REAL fp32 input via half-length complex FFT (M = 2^25):
//   z[n] = x[2n] + i x[2n+1]  (free reinterpret), Z = FFT_M(z), Hermitian unpack.
//   P1:  radix-256, s=1      z -> D   (d_out as complex scratch)   [verified]
//   P2:  radix-256, s=256    D -> B   (g_buf)                      [verified]
//   P3U: PERSISTENT radix-512 final (s=2^16) fused with unpack, cp.async
//        double-buffered: 148 blocks x 512 threads, 3 smem half-buffers,
//        prefetch of pair i+1 overlaps FFT+unpack of pair i.

#define NFFT  (1u << 26)
#define MFFT  (1u << 25)
#define M256  (1u << 17)   // MFFT / 256
#define S512  (1u << 16)   // MFFT / 512
#define NPAIR 2049u        // ceil((S512/2)/16) + 1 self-mirror chunk
#define NGRID 148u
#define TWO_PI 6.28318530717958647692f
#define INVM  (1.0f / 33554432.0f)
#define INVN  (1.0f / 67108864.0f)
#define GSK   513u                 // group stride in float2 (odd -> no conflicts)
#define HBUF  (16u * GSK)          // one half-chunk buffer (16 groups)

static __device__ float2 g_buf[MFFT];  // 256 MB scratch (sanctioned)

// exp(-2*pi*i*j/256), j = 0..15
__constant__ float2 c_w256[16] = {
    { 1.00000000000000000f, -0.00000000000000000f},
    { 0.99969881869620422f, -0.02454122852291229f},
    { 0.99879545620517241f, -0.04906767432741801f},
    { 0.99729045667869021f, -0.07356456359966743f},
    { 0.99518472667219693f, -0.09801714032956060f},
    { 0.99247953459870997f, -0.12241067519921620f},
    { 0.98917650996478101f, -0.14673047445536175f},
    { 0.98527764238894122f, -0.17096188876030122f},
    { 0.98078528040323044f, -0.19509032201612825f},
    { 0.97570213003852857f, -0.21910124015686980f},
    { 0.97003125319454397f, -0.24298017990326390f},
    { 0.96377606579543984f, -0.26671275747489837f},
    { 0.95694033573220882f, -0.29028467725446233f},
    { 0.94952818059303667f, -0.31368174039889152f},
    { 0.94154406518302081f, -0.33688985339222005f},
    { 0.93299279883473896f, -0.35989503653498817f}
};
// exp(-2*pi*i*k/32), k = 0..15
__constant__ float2 c_w32[16] = {
    { 1.00000000000000000f, -0.00000000000000000f},
    { 0.98078528040323045f, -0.19509032201612827f},
    { 0.92387953251128676f, -0.38268343236508977f},
    { 0.83146961230254524f, -0.55557023301960222f},
    { 0.70710678118654752f, -0.70710678118654752f},
    { 0.55557023301960222f, -0.83146961230254524f},
    { 0.38268343236508977f, -0.92387953251128676f},
    { 0.19509032201612827f, -0.98078528040323045f},
    { 0.00000000000000000f, -1.00000000000000000f},
    {-0.19509032201612827f, -0.98078528040323045f},
    {-0.38268343236508977f, -0.92387953251128676f},
    {-0.55557023301960222f, -0.83146961230254524f},
    {-0.70710678118654752f, -0.70710678118654752f},
    {-0.83146961230254524f, -0.55557023301960222f},
    {-0.92387953251128676f, -0.38268343236508977f},
    {-0.98078528040323045f, -0.19509032201612827f}
};

__device__ __forceinline__ float2 cmul(float2 a, float2 b) {
    return make_float2(a.x * b.x - a.y * b.y, a.x * b.y + a.y * b.x);
}
__device__ __forceinline__ float2 cadd(float2 a, float2 b) {
    return make_float2(a.x + b.x, a.y + b.y);
}
__device__ __forceinline__ float2 csub(float2 a, float2 b) {
    return make_float2(a.x - b.x, a.y - b.y);
}
__device__ __forceinline__ float2 cmul_negi(float2 a) { return make_float2(a.y, -a.x); }
__device__ __forceinline__ float2 cmul_posi(float2 a) { return make_float2(-a.y, a.x); }

// In-place forward DFT-16, natural order in/out (verified rounds 2-9).
__device__ __forceinline__ void dft16(float2 a[16]) {
    const float C1 = 0.92387953251128675613f;
    const float S1 = 0.38268343236508977173f;
    const float H  = 0.70710678118654752440f;
    const float2 W1 = make_float2( C1, -S1);
    const float2 W2 = make_float2(  H,  -H);
    const float2 W3 = make_float2( S1, -C1);
    const float2 W4 = make_float2(0.f, -1.f);
    const float2 W6 = make_float2( -H,  -H);
    const float2 W9 = make_float2(-C1,  S1);
    float2 b[16];
#pragma unroll
    for (int r1 = 0; r1 < 4; ++r1) {
        float2 x0 = a[r1], x1 = a[r1 + 4], x2 = a[r1 + 8], x3 = a[r1 + 12];
        float2 e = cadd(x0, x2), f = csub(x0, x2);
        float2 g = cadd(x1, x3), h = csub(x1, x3);
        b[r1 * 4 + 0] = cadd(e, g);
        b[r1 * 4 + 1] = cadd(f, cmul_negi(h));
        b[r1 * 4 + 2] = csub(e, g);
        b[r1 * 4 + 3] = cadd(f, cmul_posi(h));
    }
    b[5]  = cmul(b[5],  W1);
    b[6]  = cmul(b[6],  W2);
    b[7]  = cmul(b[7],  W3);
    b[9]  = cmul(b[9],  W2);
    b[10] = cmul(b[10], W4);
    b[11] = cmul(b[11], W6);
    b[13] = cmul(b[13], W3);
    b[14] = cmul(b[14], W6);
    b[15] = cmul(b[15], W9);
#pragma unroll
    for (int k1 = 0; k1 < 4; ++k1) {
        float2 x0 = b[k1], x1 = b[4 + k1], x2 = b[8 + k1], x3 = b[12 + k1];
        float2 e = cadd(x0, x2), f = csub(x0, x2);
        float2 g = cadd(x1, x3), h = csub(x1, x3);
        a[k1 + 0]  = cadd(e, g);
        a[k1 + 4]  = cadd(f, cmul_negi(h));
        a[k1 + 8]  = csub(e, g);
        a[k1 + 12] = cadd(f, cmul_posi(h));
    }
}

__device__ __forceinline__ unsigned swz(unsigned l) { return l + (l >> 8); }

// ---------------------------------------------------------------------------
// P1: radix-256, s=1, complex input (verified rounds 7-9).
// ---------------------------------------------------------------------------
__global__ void __launch_bounds__(256) fft256_first(const float2* __restrict__ x,
                                                    float2* __restrict__ y) {
    __shared__ float2 sm[4112];
    unsigned tid = threadIdx.x;
    unsigned g = tid & 15u, j2 = tid >> 4;
    unsigned t = blockIdx.x * 16u + g;

    float2 a[16];
#pragma unroll
    for (int i = 0; i < 16; ++i) a[i] = x[t + (16u * (unsigned)i + j2) * M256];
    dft16(a);

    float sn, cs;
    __sincosf(-TWO_PI * (float)t * INVM, &sn, &cs);
    float2 wg = make_float2(cs, sn);
    float2 w1 = cmul(c_w256[j2], wg);
    float2 w = make_float2(1.f, 0.f);
#pragma unroll
    for (int k1 = 0; k1 < 16; ++k1) {
        sm[swz(tid + 256u * (unsigned)k1)] = cmul(a[k1], w);
        w = cmul(w, w1);
    }
    __syncthreads();

    unsigned k1p = tid >> 4;
#pragma unroll
    for (int j = 0; j < 16; ++j)
        a[j] = sm[swz(256u * k1p + 16u * (unsigned)j + g)];
    dft16(a);

    float2 w2 = cmul(wg, wg);
    w2 = cmul(w2, w2); w2 = cmul(w2, w2); w2 = cmul(w2, w2);  // wg^16
    float2 r[16];
    w = make_float2(1.f, 0.f);
#pragma unroll
    for (int k2 = 0; k2 < 16; ++k2) { r[k2] = cmul(a[k2], w); w = cmul(w, w2); }

    __syncthreads();
#pragma unroll
    for (int k2 = 0; k2 < 16; ++k2)
        sm[swz(256u * g + k1p + 16u * (unsigned)k2)] = r[k2];
    __syncthreads();

    unsigned base = blockIdx.x * 4096u;
#pragma unroll
    for (int i = 0; i < 16; ++i) {
        unsigned m = tid + 256u * (unsigned)i;
        y[base + m] = sm[swz(m)];
    }
}

// ---------------------------------------------------------------------------
// P2: radix-256 mid stage, log2s = 8 (verified rounds 7-9).
// ---------------------------------------------------------------------------
__global__ void __launch_bounds__(256) fft256_mid(const float2* __restrict__ x,
                                                  float2* __restrict__ y,
                                                  int log2s) {
    __shared__ float2 sm[4112];
    unsigned tid = threadIdx.x;
    unsigned g = tid & 15u, j2 = tid >> 4;
    unsigned t = blockIdx.x * 16u + g;
    unsigned s = 1u << log2s;
    unsigned q = t & (s - 1u);
    unsigned ps = t - q;

    float2 a[16];
#pragma unroll
    for (int i = 0; i < 16; ++i) a[i] = x[t + (16u * (unsigned)i + j2) * M256];
    dft16(a);

    float sn, cs;
    __sincosf(-TWO_PI * (float)ps * INVM, &sn, &cs);
    float2 wg = make_float2(cs, sn);
    float2 w1 = cmul(c_w256[j2], wg);
    float2 w = make_float2(1.f, 0.f);
#pragma unroll
    for (int k1 = 0; k1 < 16; ++k1) {
        sm[swz(tid + 256u * (unsigned)k1)] = cmul(a[k1], w);
        w = cmul(w, w1);
    }
    __syncthreads();

    unsigned k1p = tid >> 4;
#pragma unroll
    for (int j = 0; j < 16; ++j)
        a[j] = sm[swz(256u * k1p + 16u * (unsigned)j + g)];
    dft16(a);

    float2 w2 = cmul(wg, wg);
    w2 = cmul(w2, w2); w2 = cmul(w2, w2); w2 = cmul(w2, w2);
    unsigned base = q + (ps << 8) + (k1p << log2s);
    w = make_float2(1.f, 0.f);
#pragma unroll
    for (int k2 = 0; k2 < 16; ++k2) {
        y[base + ((unsigned)k2 << (log2s + 4))] = cmul(a[k2], w);
        w = cmul(w, w2);
    }
}

// ----------------------------- cp.async helpers -----------------------------
__device__ __forceinline__ void cp_async8(void* smem_dst, const void* gmem_src) {
    unsigned d = (unsigned)__cvta_generic_to_shared(smem_dst);
    asm volatile("cp.async.ca.shared.global [%0], [%1], 8;\n" :: "r"(d), "l"(gmem_src));
}
__device__ __forceinline__ void cp_commit() {
    asm volatile("cp.async.commit_group;\n");
}
__device__ __forceinline__ void cp_wait1() {
    asm volatile("cp.async.wait_group 1;\n");
}
__device__ __forceinline__ void cp_wait0() {
    asm volatile("cp.async.wait_group 0;\n");
}

// ---------------------------------------------------------------------------
// P3U persistent: radix-512 final stage fused with Hermitian unpack,
// cp.async double-buffered across pairs. Thread map (round-8 verified,
// conflict-free): g = tid&15 fast lane, u = tid>>4 in [0,32).
// Pair p: half A holds groups tA = 16p+g; half B the Hermitian mirrors
// tB = (S512 - 16p - 15 + g) mod S512 (group 15-gA mirrors gA).
// ---------------------------------------------------------------------------
__device__ __forceinline__ void p3_load_half(const float2* __restrict__ x,
                                             float2* __restrict__ sm,
                                             unsigned slot, unsigned p, int half,
                                             unsigned g, unsigned u) {
    unsigned t = half ? ((S512 - 16u * p - 15u + g) & (S512 - 1u))
                      : (16u * p + g);
    float2* dst = sm + slot * HBUF + g * GSK;
#pragma unroll
    for (int j = 0; j < 16; ++j) {
        unsigned r = u + 32u * (unsigned)j;
        cp_async8(dst + r, x + t + r * S512);
    }
}

// In-place 512-point FFT of all 16 groups in one slot (16x16x2 layers).
// Caller guarantees a __syncthreads() before entry (input data visible).
__device__ __forceinline__ void p3_fft_half(float2* __restrict__ sm,
                                            unsigned slot, unsigned g, unsigned u) {
    float2* gb = sm + slot * HBUF + g * GSK;
    float2 a[16];
    // SA: read input samples r = u + 32 j
#pragma unroll
    for (int j = 0; j < 16; ++j) a[j] = gb[u + 32u * (unsigned)j];
    dft16(a);
    __syncthreads();  // all input reads done before in-place overwrite
    {
        float sn, cs;
        __sincosf(-TWO_PI * (float)u * (1.0f / 512.0f), &sn, &cs);
        float2 wa = make_float2(cs, sn), w = make_float2(1.f, 0.f);
#pragma unroll
        for (int k = 0; k < 16; ++k) {
            gb[16u * u + (unsigned)k] = cmul(a[k], w);
            w = cmul(w, wa);
        }
    }
    __syncthreads();
    // SB: radix-16, s=16
#pragma unroll
    for (int j = 0; j < 16; ++j) a[j] = gb[u + 32u * (unsigned)j];
    dft16(a);
    __syncthreads();
    {
        unsigned q15 = u & 15u, p2 = u >> 4;
#pragma unroll
        for (int k = 0; k < 16; ++k) {
            float2 v = (p2 == 0u) ? a[k] : cmul(a[k], c_w32[k]);
            gb[q15 + 256u * p2 + 16u * (unsigned)k] = v;
        }
    }
    __syncthreads();
    // SC: radix-2, s=256, same-thread in-place
#pragma unroll
    for (int i = 0; i < 8; ++i) {
        unsigned t2 = u + 32u * (unsigned)i;
        float2 b0 = gb[t2];
        float2 b1 = gb[t2 + 256u];
        gb[t2]        = cadd(b0, b1);
        gb[t2 + 256u] = csub(b0, b1);
    }
}

// Hermitian unpack of pair p from slots (sA, sB); verified round-8 algebra.
__device__ __forceinline__ void p3_unpack(const float2* __restrict__ sm,
                                          unsigned sA, unsigned sB,
                                          unsigned p, float* __restrict__ out,
                                          unsigned g, unsigned u) {
    const float2* gbA = sm + sA * HBUF + g * GSK;
    const float2* gbB = sm + sB * HBUF + (15u - g) * GSK;
    const unsigned t = 16u * p + g;
    const bool tzero = (t == 0u);

    float sn, cs;
    __sincosf(-TWO_PI * (float)(t + u * S512) * INVN, &sn, &cs);
    float2 W = make_float2(cs, sn);
    const float2 Winc = c_w32[1];  // e^{-2pi i/32}: k += 32 step

#pragma unroll
    for (int j = 0; j < 16; ++j) {
        unsigned k = u + 32u * (unsigned)j;
        float2 Zk = gbA[k];
        unsigned kp = tzero ? ((512u - k) & 511u) : (511u - k);
        float2 Zm = gbB[kp];

        float2 A = make_float2(0.5f * (Zk.x + Zm.x), 0.5f * (Zk.y - Zm.y));
        float2 C = make_float2(0.5f * (Zk.x - Zm.x), 0.5f * (Zk.y + Zm.y));
        float2 B = make_float2(C.y, -C.x);
        float2 WB = cmul(W, B);
        float2 P = cadd(A, WB);
        float2 Q = csub(A, WB);

        unsigned m = t + k * S512;               // [0, M)
        unsigned i3 = (NFFT - m) & (NFFT - 1u);  // N - m (mod N)
        unsigned i2 = MFFT - m;
        unsigned i4 = MFFT + m;

        out[m]  = P.x;   out[NFFT + m]  = P.y;
        out[i3] = P.x;   out[NFFT + i3] = -P.y;
        out[i2] = Q.x;   out[NFFT + i2] = -Q.y;
        out[i4] = Q.x;   out[NFFT + i4] = Q.y;

        W = cmul(W, Winc);
    }
}

__global__ void __launch_bounds__(512, 1) fft512_unpack_persist(
        const float2* __restrict__ x, float* __restrict__ out) {
    extern __shared__ float2 sm[];
    const unsigned tid = threadIdx.x;
    const unsigned g = tid & 15u, u = tid >> 4;

    unsigned p = blockIdx.x;
    if (p >= NPAIR) return;

    // Prologue: stream both halves of the first pair.
    p3_load_half(x, sm, 0u, p, 0, g, u); cp_commit();
    p3_load_half(x, sm, 1u, p, 1, g, u); cp_commit();
    unsigned sA = 0u, sB = 1u, sF = 2u;

    for (;;) {
        unsigned pn = p + NGRID;
        bool has_next = (pn < NPAIR);
        if (has_next) { p3_load_half(x, sm, sF, pn, 0, g, u); cp_commit(); }

        if (has_next) cp_wait1(); else cp_wait0();
        __syncthreads();  // current pair's halves visible to all threads

        p3_fft_half(sm, sA, g, u);
        p3_fft_half(sm, sB, g, u);
        __syncthreads();  // SC results visible before cross-group unpack reads

        p3_unpack(sm, sA, sB, p, out, g, u);
        __syncthreads();  // unpack reads done before slot sA is reused

        if (!has_next) break;
        p3_load_half(x, sm, sA, pn, 1, g, u); cp_commit();  // B(pn) -> freed sA

        unsigned oldA = sA;
        sA = sF;      // holds A(pn)
        sF = sB;      // freed after unpack; prefetch target next iter
        sB = oldA;    // receiving B(pn)
        p = pn;
    }
}

// ---------------------------------------------------------------------------
// Schedule: P1: z -> D (d_out scratch); P2: D -> B (g_buf); P3U: B -> out.
// P3U reads only g_buf, writes only d_out: no aliasing hazard.
// ---------------------------------------------------------------------------
extern "C" void kernel_launch(void* const* d_in, const int* in_sizes, int n_in,
                              void* d_out, int out_size) {
    const float2* z = (const float2*)d_in[0];   // N reals = M complex (free pack)
    float* out = (float*)d_out;
    float2* D = (float2*)d_out;                 // M float2 scratch fits in out
    float2* B = nullptr;
    cudaGetSymbolAddress((void**)&B, g_buf);

    const size_t smem3 = (size_t)(3u * HBUF) * sizeof(float2);  // 196,992 B
    cudaFuncSetAttribute(fft512_unpack_persist,
                         cudaFuncAttributeMaxDynamicSharedMemorySize, (int)smem3);

    fft256_first <<<M256 / 16u, 256>>>(z, D);            // 8192 blocks
    fft256_mid   <<<M256 / 16u, 256>>>(D, B, 8);         // 8192 blocks
    fft512_unpack_persist<<<NGRID, 512, smem3>>>(B, out);
}